// round 1
// baseline (speedup 1.0000x reference)
#include <cuda_runtime.h>

#define DEV_INLINE __device__ __forceinline__

constexpr int NK = 2, NH = 4, NNODE = 4096, ND = 64, NO = 64, NUSER = 4000;
constexpr int KH = NK * NH;                  // 8
constexpr int R = 64;                        // rows per attention block
constexpr int TJ = 32;                       // column tile
constexpr int JSPLIT = 2;                    // split j-range for occupancy
constexpr int ATTN_THREADS = 256;

// ---------------- scratch (static device globals; no allocation) -------------
__device__ float g_hp[(size_t)KH * NNODE * NO];                 // h_prime (k,h,n,o)  8 MB
__device__ float g_srcv[KH * NNODE], g_a[KH * NNODE], g_a2[KH * NNODE];
__device__ float g_dstv[KH * NNODE], g_b[KH * NNODE], g_b2[KH * NNODE];
__device__ float g_num[(size_t)JSPLIT * KH * NNODE * NO];       // 16 MB
__device__ float g_den[JSPLIT * KH * NNODE];
__device__ float g_out[(size_t)NK * NNODE * NO];                // 2 MB

// ---------------- packed fp32x2 helpers --------------------------------------
DEV_INLINE unsigned long long pk2(float a, float b) {
    unsigned long long r;
    asm("mov.b64 %0, {%1, %2};" : "=l"(r) : "f"(a), "f"(b));
    return r;
}
DEV_INLINE float2 upk2(unsigned long long v) {
    float2 r;
    asm("mov.b64 {%0, %1}, %2;" : "=f"(r.x), "=f"(r.y) : "l"(v));
    return r;
}
DEV_INLINE void fma2(unsigned long long& d, unsigned long long a, unsigned long long b) {
    asm("fma.rn.f32x2 %0, %1, %2, %0;" : "+l"(d) : "l"(a), "l"(b));
}

// ---------------- stage 1a: h_prime = h @ w[k,h] ----------------------------
__global__ void prep_gemm(const float* __restrict__ hin, const float* __restrict__ w) {
    __shared__ float s_w[ND][NO];
    __shared__ float s_h[64][ND];
    int t  = threadIdx.x;
    int kh = blockIdx.x >> 6;            // 0..7
    int n0 = (blockIdx.x & 63) * 64;     // row tile
    const float* wk   = w + (size_t)kh * ND * NO;
    const float* hsrc = hin + (size_t)n0 * ND;
    for (int q = t; q < ND * NO; q += 256) ((float*)s_w)[q] = wk[q];
    for (int q = t; q < 64 * ND; q += 256) ((float*)s_h)[q] = hsrc[q];
    __syncthreads();
    int tr = t >> 4, tc = t & 15;        // 4x4 output tile per thread
    float acc[4][4] = {};
    for (int d = 0; d < ND; d++) {
        float4 wv = *(const float4*)&s_w[d][tc * 4];
        #pragma unroll
        for (int r = 0; r < 4; r++) {
            float hv = s_h[tr * 4 + r][d];
            acc[r][0] += hv * wv.x; acc[r][1] += hv * wv.y;
            acc[r][2] += hv * wv.z; acc[r][3] += hv * wv.w;
        }
    }
    #pragma unroll
    for (int r = 0; r < 4; r++) {
        float4 v = make_float4(acc[r][0], acc[r][1], acc[r][2], acc[r][3]);
        *(float4*)&g_hp[((size_t)kh * NNODE + n0 + tr * 4 + r) * NO + tc * 4] = v;
    }
}

// ---------------- stage 1b: tanh dots + separable exp tables -----------------
__global__ void prep_rowstats(const float* __restrict__ a_src, const float* __restrict__ a_dst) {
    __shared__ float sas[NO], sad[NO];
    int t  = threadIdx.x;
    int kh = blockIdx.x >> 4;
    int n  = ((blockIdx.x & 15) << 8) + t;
    if (t < NO)           sas[t]      = a_src[kh * NO + t];
    else if (t < 2 * NO)  sad[t - NO] = a_dst[kh * NO + t - NO];
    __syncthreads();
    const float* row = g_hp + ((size_t)kh * NNODE + n) * NO;
    float ss = 0.f, dd = 0.f;
    #pragma unroll
    for (int o = 0; o < NO; o++) {
        float tv = tanhf(row[o]);
        ss += tv * sas[o];
        dd += tv * sad[o];
    }
    int idx = kh * NNODE + n;
    g_srcv[idx] = ss; g_a[idx] = expf(ss); g_a2[idx] = expf(0.2f * ss);
    g_dstv[idx] = dd; g_b[idx] = expf(dd); g_b2[idx] = expf(0.2f * dd);
}

// ---------------- stage 2: streaming masked softmax + PV ---------------------
struct __align__(16) AttnSmem {
    float  adjT[TJ][R + 1];          // [jj][i], padded vs bank conflicts
    float  p[NH][TJ][R];             // attention weights (unnormalized)
    float4 hp4[NH][TJ * NO / 4];     // h_prime column tile
    float  srcv[NH][R], a[NH][R], a2[NH][R];
    float  dstv[NH][TJ], b[NH][TJ], b2[NH][TJ];
};

__global__ void __launch_bounds__(ATTN_THREADS, 2)
attn_kernel(const float* __restrict__ adj) {
    extern __shared__ char smem_raw[];
    AttnSmem& s = *reinterpret_cast<AttnSmem*>(smem_raw);
    int t  = threadIdx.x;
    int bb = blockIdx.x;                 // 256 blocks
    int js = bb & 1;
    int rt = (bb >> 1) & 63;
    int k  = bb >> 7;
    int i0   = rt * R;
    int jbeg = js * (NNODE / JSPLIT);
    int jend = jbeg + NNODE / JSPLIT;

    int hA = t >> 6, iA = t & 63;        // role A: p-construction (one row each)
    int g  = t & 63;                     // role B: PV, 8i x 8o tile per thread
    int o_base = (g & 7) * 8;
    int i_base = (g >> 3) * 8;
    int warp = t >> 5, lane = t & 31;

    {   // per-row constants (fixed for this block)
        int idx = (k * NH + hA) * NNODE + i0 + iA;
        s.srcv[hA][iA] = g_srcv[idx];
        s.a[hA][iA]    = g_a[idx];
        s.a2[hA][iA]   = g_a2[idx];
    }
    __syncthreads();
    float srci = s.srcv[hA][iA], ai = s.a[hA][iA], a2i = s.a2[hA][iA];
    float den = 0.f;

    unsigned long long acc[8][4];        // 8 rows x 4 o-pairs (fp32x2)
    #pragma unroll
    for (int i = 0; i < 8; i++)
        #pragma unroll
        for (int c = 0; c < 4; c++) acc[i][c] = 0ull;

    for (int j0 = jbeg; j0 < jend; j0 += TJ) {
        __syncthreads();
        {   // adjacency tile (transposed into smem), coalesced 128B rows
            const float* arow = adj + (size_t)k * NNODE * NNODE
                                    + (size_t)(i0 + warp * 8) * NNODE + j0 + lane;
            #pragma unroll
            for (int r8 = 0; r8 < 8; r8++)
                s.adjT[lane][warp * 8 + r8] = arow[(size_t)r8 * NNODE];
        }
        {   // h_prime column tile, contiguous per head
            const float4* src4 = (const float4*)(g_hp + ((size_t)(k * NH + hA) * NNODE + j0) * NO);
            #pragma unroll
            for (int q = 0; q < 8; q++)
                s.hp4[hA][q * 64 + iA] = src4[q * 64 + iA];
        }
        if (t < NH * TJ) {
            int hh = t >> 5, jj = t & 31;
            int idx = (k * NH + hh) * NNODE + j0 + jj;
            s.dstv[hh][jj] = g_dstv[idx];
            s.b[hh][jj]    = g_b[idx];
            s.b2[hh][jj]   = g_b2[idx];
        }
        __syncthreads();
        // p[i][j] = adj * (src+dst >= 0 ? e^src e^dst : e^.2src e^.2dst) -- no MUFU
        #pragma unroll 8
        for (int jj = 0; jj < TJ; jj++) {
            float sg = srci + s.dstv[hA][jj];
            float e  = (sg >= 0.f) ? ai * s.b[hA][jj] : a2i * s.b2[hA][jj];
            float pv = s.adjT[jj][iA] * e;
            s.p[hA][jj][iA] = pv;
            den += pv;
        }
        __syncthreads();
        // PV rank-1 updates with packed fp32x2 FMAs
        #pragma unroll 4
        for (int jj = 0; jj < TJ; jj++) {
            const ulonglong2* hpp = (const ulonglong2*)(&s.hp4[hA][jj * 16 + (o_base >> 2)]);
            ulonglong2 u0 = hpp[0], u1 = hpp[1];
            float4 pA = *(const float4*)&s.p[hA][jj][i_base];
            float4 pB = *(const float4*)&s.p[hA][jj][i_base + 4];
            float pv[8] = {pA.x, pA.y, pA.z, pA.w, pB.x, pB.y, pB.z, pB.w};
            #pragma unroll
            for (int i = 0; i < 8; i++) {
                unsigned long long pp = pk2(pv[i], pv[i]);
                fma2(acc[i][0], pp, u0.x);
                fma2(acc[i][1], pp, u0.y);
                fma2(acc[i][2], pp, u1.x);
                fma2(acc[i][3], pp, u1.y);
            }
        }
    }
    g_den[((size_t)js * KH + k * NH + hA) * NNODE + i0 + iA] = den;
    float* np = g_num + ((size_t)js * KH + k * NH + hA) * NNODE * NO;
    #pragma unroll
    for (int i = 0; i < 8; i++) {
        int n = i0 + i_base + i;
        #pragma unroll
        for (int c = 0; c < 4; c++) {
            float2 v = upk2(acc[i][c]);
            *(float2*)&np[(size_t)n * NO + o_base + c * 2] = v;
        }
    }
}

// ---------------- stage 2b: combine j-splits, normalize, head mean -----------
__global__ void combine_kernel() {
    int idx = blockIdx.x * 256 + threadIdx.x;   // < NK*NNODE*NO
    int o = idx & 63;
    int n = (idx >> 6) & (NNODE - 1);
    int k = idx >> 18;
    constexpr size_t NUMS = (size_t)KH * NNODE * NO;
    constexpr int    DENS = KH * NNODE;
    float acc = 0.f;
    #pragma unroll
    for (int h = 0; h < NH; h++) {
        size_t base = (((size_t)(k * NH + h)) * NNODE + n) * NO + o;
        float num = g_num[base] + g_num[NUMS + base];
        int   di  = (k * NH + h) * NNODE + n;
        float d   = g_den[di] + g_den[DENS + di];
        acc += num / d;
    }
    g_out[idx] = 0.25f * acc;
}

// ---------------- stage 3: fc + log_softmax over 2 classes -------------------
__global__ void final_kernel(const float* __restrict__ fcw, const float* __restrict__ fcb,
                             float* __restrict__ outp) {
    __shared__ float sw[2][128];
    __shared__ float sb[2];
    int t = threadIdx.x;
    for (int q = t; q < 256; q += 128) ((float*)sw)[q] = fcw[q];
    if (t < 2) sb[t] = fcb[t];
    __syncthreads();
    int n = blockIdx.x * 128 + t;
    if (n >= NUSER) return;
    float l0 = sb[0], l1 = sb[1];
    #pragma unroll
    for (int k = 0; k < NK; k++) {
        const float* x = g_out + ((size_t)k * NNODE + n) * NO;
        #pragma unroll
        for (int o = 0; o < NO; o++) {
            float xv = x[o];
            l0 += xv * sw[0][k * 64 + o];
            l1 += xv * sw[1][k * 64 + o];
        }
    }
    float m   = fmaxf(l0, l1);
    float lse = m + logf(expf(l0 - m) + expf(l1 - m));
    outp[n * 2]     = l0 - lse;
    outp[n * 2 + 1] = l1 - lse;
}

// ---------------- launch ------------------------------------------------------
extern "C" void kernel_launch(void* const* d_in, const int* in_sizes, int n_in,
                              void* d_out, int out_size) {
    const float* h     = (const float*)d_in[0];
    const float* hadj  = (const float*)d_in[1];
    const float* w     = (const float*)d_in[2];
    const float* a_src = (const float*)d_in[3];
    const float* a_dst = (const float*)d_in[4];
    const float* fc_w  = (const float*)d_in[5];
    const float* fc_b  = (const float*)d_in[6];
    float* outp = (float*)d_out;

    prep_gemm<<<KH * (NNODE / 64), 256>>>(h, w);
    prep_rowstats<<<KH * (NNODE / 256), 256>>>(a_src, a_dst);

    int smem = (int)sizeof(AttnSmem);
    cudaFuncSetAttribute(attn_kernel, cudaFuncAttributeMaxDynamicSharedMemorySize, smem);
    attn_kernel<<<NK * (NNODE / R) * JSPLIT, ATTN_THREADS, smem>>>(hadj);

    combine_kernel<<<NK * NNODE * NO / 256, 256>>>();
    final_kernel<<<NNODE / 128, 128>>>(fc_w, fc_b, outp);
}

// round 4
// speedup vs baseline: 3.0971x; 3.0971x over previous
#include <cuda_runtime.h>
#include <cuda_bf16.h>
#include <cstdint>

#define DEV_INLINE __device__ __forceinline__

constexpr int NK = 2, NH = 4, NNODE = 4096, ND = 64, NO = 64, NUSER = 4000;
constexpr int KH = NK * NH;
constexpr int JCHUNK = 64, NCHUNK = NNODE / JCHUNK;   // 64 chunks
constexpr int PSTR = 144;                             // padded bf16 tile row stride (bytes)

// ---------------- scratch ----------------------------------------------------
__device__ float g_hp[(size_t)KH * NNODE * NO];
__device__ __nv_bfloat16 g_hpT[(size_t)KH * NO * NNODE];   // V^T bf16: (k,h,o,n)
__device__ float g_srcv[KH * NNODE], g_ea[KH * NNODE], g_ea2[KH * NNODE];
__device__ float g_dstv[KH * NNODE], g_eb[KH * NNODE], g_eb2[KH * NNODE];
__device__ float g_out[(size_t)NK * NNODE * NO];

// ---------------- helpers ----------------------------------------------------
DEV_INLINE uint32_t smem_u32(const void* p) {
    uint32_t a;
    asm("{ .reg .u64 t; cvta.to.shared.u64 t, %1; cvt.u32.u64 %0, t; }" : "=r"(a) : "l"(p));
    return a;
}
DEV_INLINE void ldsm4(uint32_t* r, uint32_t a) {
    asm volatile("ldmatrix.sync.aligned.m8n8.x4.shared.b16 {%0,%1,%2,%3}, [%4];"
                 : "=r"(r[0]), "=r"(r[1]), "=r"(r[2]), "=r"(r[3]) : "r"(a));
}
DEV_INLINE void mma16816(float* c, const uint32_t* a, const uint32_t* b) {
    asm volatile(
        "mma.sync.aligned.m16n8k16.row.col.f32.bf16.bf16.f32 "
        "{%0,%1,%2,%3}, {%4,%5,%6,%7}, {%8,%9}, {%0,%1,%2,%3};"
        : "+f"(c[0]), "+f"(c[1]), "+f"(c[2]), "+f"(c[3])
        : "r"(a[0]), "r"(a[1]), "r"(a[2]), "r"(a[3]), "r"(b[0]), "r"(b[1]));
}
DEV_INLINE uint32_t cvt_bf16x2(float hi, float lo) {
    uint32_t r;
    asm("cvt.rn.bf16x2.f32 %0, %1, %2;" : "=r"(r) : "f"(hi), "f"(lo));
    return r;
}

// ---------------- stage 1a: h_prime GEMM + bf16 transposed V -----------------
__global__ void prep_gemm(const float* __restrict__ hin, const float* __restrict__ w) {
    __shared__ float s_w[ND][NO];
    __shared__ float s_h[64][66];
    int t = threadIdx.x;
    int kh = blockIdx.x >> 6;
    int n0 = (blockIdx.x & 63) * 64;
    const float* wk = w + (size_t)kh * ND * NO;
    const float* hsrc = hin + (size_t)n0 * ND;
    for (int q = t; q < ND * NO; q += 256) ((float*)s_w)[q] = wk[q];
    for (int q = t; q < 64 * ND; q += 256) s_h[q >> 6][q & 63] = hsrc[q];
    __syncthreads();
    int tr = t >> 4, tc = t & 15;
    float acc[4][4] = {};
    for (int d = 0; d < ND; d++) {
        float4 wv = *(const float4*)&s_w[d][tc * 4];
        #pragma unroll
        for (int r = 0; r < 4; r++) {
            float hv = s_h[tr * 4 + r][d];
            acc[r][0] += hv * wv.x; acc[r][1] += hv * wv.y;
            acc[r][2] += hv * wv.z; acc[r][3] += hv * wv.w;
        }
    }
    #pragma unroll
    for (int r = 0; r < 4; r++)
        *(float4*)&g_hp[((size_t)kh * NNODE + n0 + tr * 4 + r) * NO + tc * 4] =
            make_float4(acc[r][0], acc[r][1], acc[r][2], acc[r][3]);
    __syncthreads();
    #pragma unroll
    for (int r = 0; r < 4; r++)
        #pragma unroll
        for (int c = 0; c < 4; c++)
            s_h[tc * 4 + c][tr * 4 + r] = acc[r][c];
    __syncthreads();
    int o = t >> 2, seg = t & 3;
    uint32_t pk[8];
    #pragma unroll
    for (int e = 0; e < 8; e++)
        pk[e] = cvt_bf16x2(s_h[o][seg * 16 + 2 * e + 1], s_h[o][seg * 16 + 2 * e]);
    uint4* dst = (uint4*)((char*)g_hpT + (((size_t)kh * NO + o) * NNODE + n0 + seg * 16) * 2);
    dst[0] = make_uint4(pk[0], pk[1], pk[2], pk[3]);
    dst[1] = make_uint4(pk[4], pk[5], pk[6], pk[7]);
}

// ---------------- stage 1b: tanh dots + separable exp tables -----------------
__global__ void prep_rowstats(const float* __restrict__ a_src, const float* __restrict__ a_dst) {
    __shared__ float sas[NO], sad[NO];
    int t = threadIdx.x;
    int kh = blockIdx.x >> 4;
    int n = ((blockIdx.x & 15) << 8) + t;
    if (t < NO)          sas[t] = a_src[kh * NO + t];
    else if (t < 2 * NO) sad[t - NO] = a_dst[kh * NO + t - NO];
    __syncthreads();
    const float* row = g_hp + ((size_t)kh * NNODE + n) * NO;
    float ss = 0.f, dd = 0.f;
    #pragma unroll
    for (int o = 0; o < NO; o++) {
        float tv = tanhf(row[o]);
        ss += tv * sas[o];
        dd += tv * sad[o];
    }
    int idx = kh * NNODE + n;
    g_srcv[idx] = ss; g_ea[idx] = expf(ss); g_ea2[idx] = expf(0.2f * ss);
    g_dstv[idx] = dd; g_eb[idx] = expf(dd); g_eb2[idx] = expf(0.2f * dd);
}

// ---------------- stage 2: fused attention (construct + HMMA) ----------------
constexpr int OFF_SRCSV = 0;                 // [4][64] f32
constexpr int OFF_SRCEA = 1024;              // [4][64] float2 (ea, ea2)
constexpr int OFF_DTBL  = 3072;              // [2][3][4][64] f32
constexpr int OFF_P     = 9216;              // [2][4] x 64*PSTR
constexpr int OFF_V     = 82944;             // [2][4] x 64*PSTR
constexpr int SMEM_ATTN = 156672;
constexpr int OFF_OUT   = OFF_P;             // epilogue reuse: [4][64][64] f32
constexpr int OFF_DEN   = OFF_P + 65536;     // [4][64] f32

__global__ void __launch_bounds__(512, 1)
attn_kernel(const float* __restrict__ adj) {
    extern __shared__ char sm[];
    uint32_t sb = smem_u32(sm);
    int t = threadIdx.x, w = t >> 5, lane = t & 31;
    int k = blockIdx.x >> 6;
    int i0 = (blockIdx.x & 63) * 64;

    int h = w >> 2, ih = (w >> 1) & 1, oh = w & 1;   // mma role
    int gr = lane >> 2, lq = lane & 3;
    uint32_t bones = (gr == 0) ? 0x3F803F80u : 0u;

    const float* adjk = adj + (size_t)k * NNODE * NNODE;

    // ---- stage src tables (once) ----
    if (t < 256) {
        int hh = t >> 6, i = t & 63;
        *(float*)(sm + OFF_SRCSV + t * 4) = g_srcv[(k * NH + hh) * NNODE + i0 + i];
    }
    {
        int p = t >> 1, comp = t & 1;
        int hh = p >> 6, i = p & 63;
        const float* sa = comp ? g_ea2 : g_ea;
        *(float*)(sm + OFF_SRCEA + p * 8 + comp * 4) = sa[(k * NH + hh) * NNODE + i0 + i];
    }
    auto stage_dst = [&](int c) {
        if (c >= NCHUNK) return;
        int buf = c & 1;
        if (t < 384) {
            #pragma unroll
            for (int u = 0; u < 2; u++) {
                int q = t * 2 + u;
                int arr = q >> 8, rest = q & 255, hh = rest >> 6, j = rest & 63;
                const float* sa = (arr == 0) ? g_dstv : (arr == 1) ? g_eb : g_eb2;
                *(float*)(sm + OFF_DTBL + buf * 3072 + (arr * 4 + hh) * 256 + j * 4) =
                    sa[(k * NH + hh) * NNODE + c * JCHUNK + j];
            }
        }
    };
    stage_dst(0);
    __syncthreads();

    float acc[2][4][4];
    float dacc[2][4];
    #pragma unroll
    for (int a = 0; a < 2; a++) {
        #pragma unroll
        for (int b = 0; b < 4; b++) {
            #pragma unroll
            for (int e = 0; e < 4; e++) acc[a][b][e] = 0.f;
            dacc[a][b] = 0.f;
        }
    }

    uint32_t aoff = (uint32_t)(((lane & 7) + 8 * ((lane >> 3) & 1)) * PSTR + (lane >> 4) * 16);
    uint32_t boff = (uint32_t)(((lane & 7) + 8 * ((lane >> 4) & 1)) * PSTR + ((lane >> 3) & 1) * 16);

    auto mma_chunk = [&](int vbuf) {
        uint32_t pb = sb + OFF_P + (vbuf * 4 + h) * 9216 + ih * 32 * PSTR;
        uint32_t vb = sb + OFF_V + (vbuf * 4 + h) * 9216 + oh * 32 * PSTR;
        #pragma unroll
        for (int ks = 0; ks < 4; ks++) {
            uint32_t a0[4], a1[4], b0[4], b1[4];
            ldsm4(a0, pb + aoff + ks * 32);
            ldsm4(a1, pb + 16 * PSTR + aoff + ks * 32);
            ldsm4(b0, vb + boff + ks * 32);
            ldsm4(b1, vb + 16 * PSTR + boff + ks * 32);
            mma16816(acc[0][0], a0, b0 + 0); mma16816(acc[0][1], a0, b0 + 2);
            mma16816(acc[0][2], a0, b1 + 0); mma16816(acc[0][3], a0, b1 + 2);
            mma16816(acc[1][0], a1, b0 + 0); mma16816(acc[1][1], a1, b0 + 2);
            mma16816(acc[1][2], a1, b1 + 0); mma16816(acc[1][3], a1, b1 + 2);
            if (oh == 0) {
                uint32_t bo[2] = {bones, bones};
                mma16816(dacc[0], a0, bo);
                mma16816(dacc[1], a1, bo);
            }
        }
    };

    for (int c = 0; c < NCHUNK; c++) {
        int buf = c & 1;
        int j0 = c * JCHUNK;
        // adj prefetch (latency overlaps mma below)
        float2 adj2[4];
        #pragma unroll
        for (int s = 0; s < 4; s++)
            adj2[s] = *(const float2*)(adjk + (size_t)(i0 + 4 * w + s) * NNODE + j0 + 2 * lane);

        if (c > 0) mma_chunk((c - 1) & 1);
        stage_dst(c + 1);

        float2 dv[4], ep[4], eq[4];
        #pragma unroll
        for (int hh = 0; hh < 4; hh++) {
            dv[hh] = *(float2*)(sm + OFF_DTBL + buf * 3072 + (0 + hh) * 256 + lane * 8);
            ep[hh] = *(float2*)(sm + OFF_DTBL + buf * 3072 + (4 + hh) * 256 + lane * 8);
            eq[hh] = *(float2*)(sm + OFF_DTBL + buf * 3072 + (8 + hh) * 256 + lane * 8);
        }
        #pragma unroll
        for (int s = 0; s < 4; s++) {
            int i = 4 * w + s;
            #pragma unroll
            for (int hh = 0; hh < 4; hh++) {
                float sv = *(float*)(sm + OFF_SRCSV + (hh * 64 + i) * 4);
                float2 ea = *(float2*)(sm + OFF_SRCEA + (hh * 64 + i) * 8);
                float sg0 = sv + dv[hh].x, sg1 = sv + dv[hh].y;
                float e0 = (sg0 >= 0.f) ? ea.x * ep[hh].x : ea.y * eq[hh].x;
                float e1 = (sg1 >= 0.f) ? ea.x * ep[hh].y : ea.y * eq[hh].y;
                *(uint32_t*)(sm + OFF_P + (buf * 4 + hh) * 9216 + i * PSTR + lane * 4) =
                    cvt_bf16x2(adj2[s].y * e1, adj2[s].x * e0);
            }
        }
        // stage V tiles for this chunk
        #pragma unroll
        for (int u = 0; u < 4; u++) {
            int q = t + 512 * u;
            int seg = q & 7, o = (q >> 3) & 63, hh = q >> 9;
            const char* src = (const char*)g_hpT +
                (((size_t)(k * NH + hh) * NO + o) * NNODE + j0) * 2 + seg * 16;
            *(uint4*)(sm + OFF_V + (buf * 4 + hh) * 9216 + o * PSTR + seg * 16) =
                *(const uint4*)src;
        }
        __syncthreads();
    }
    mma_chunk((NCHUNK - 1) & 1);
    __syncthreads();

    // ---- epilogue: fragments -> smem, normalize + head-mean, write g_out ----
    #pragma unroll
    for (int mt = 0; mt < 2; mt++) {
        #pragma unroll
        for (int nt = 0; nt < 4; nt++) {
            int row = ih * 32 + mt * 16 + gr;
            int col = oh * 32 + nt * 8 + 2 * lq;
            *(float2*)(sm + OFF_OUT + ((h * 64 + row) * 64 + col) * 4) =
                make_float2(acc[mt][nt][0], acc[mt][nt][1]);
            *(float2*)(sm + OFF_OUT + ((h * 64 + row + 8) * 64 + col) * 4) =
                make_float2(acc[mt][nt][2], acc[mt][nt][3]);
        }
        if (oh == 0 && lq == 0) {
            int row = ih * 32 + mt * 16 + gr;
            *(float*)(sm + OFF_DEN + (h * 64 + row) * 4) = dacc[mt][0];
            *(float*)(sm + OFF_DEN + (h * 64 + row + 8) * 4) = dacc[mt][2];
        }
    }
    __syncthreads();
    {
        int i = t >> 3, ob = (t & 7) * 8;
        float res[8] = {};
        #pragma unroll
        for (int hh = 0; hh < 4; hh++) {
            float inv = 0.25f / *(float*)(sm + OFF_DEN + (hh * 64 + i) * 4);
            float4 x0 = *(float4*)(sm + OFF_OUT + ((hh * 64 + i) * 64 + ob) * 4);
            float4 x1 = *(float4*)(sm + OFF_OUT + ((hh * 64 + i) * 64 + ob + 4) * 4);
            res[0] += x0.x * inv; res[1] += x0.y * inv; res[2] += x0.z * inv; res[3] += x0.w * inv;
            res[4] += x1.x * inv; res[5] += x1.y * inv; res[6] += x1.z * inv; res[7] += x1.w * inv;
        }
        float* dst = &g_out[((size_t)k * NNODE + i0 + i) * NO + ob];
        *(float4*)dst = make_float4(res[0], res[1], res[2], res[3]);
        *(float4*)(dst + 4) = make_float4(res[4], res[5], res[6], res[7]);
    }
}

// ---------------- stage 3: fc + log_softmax over 2 classes -------------------
__global__ void final_kernel(const float* __restrict__ fcw, const float* __restrict__ fcb,
                             float* __restrict__ outp) {
    __shared__ float swt[2][128];
    __shared__ float sbv[2];
    int t = threadIdx.x;
    for (int q = t; q < 256; q += 128) ((float*)swt)[q] = fcw[q];
    if (t < 2) sbv[t] = fcb[t];
    __syncthreads();
    int n = blockIdx.x * 128 + t;
    if (n >= NUSER) return;
    float l0 = sbv[0], l1 = sbv[1];
    #pragma unroll
    for (int k = 0; k < NK; k++) {
        const float* x = g_out + ((size_t)k * NNODE + n) * NO;
        #pragma unroll
        for (int o = 0; o < NO; o++) {
            float xv = x[o];
            l0 += xv * swt[0][k * 64 + o];
            l1 += xv * swt[1][k * 64 + o];
        }
    }
    float m = fmaxf(l0, l1);
    float lse = m + logf(expf(l0 - m) + expf(l1 - m));
    outp[n * 2] = l0 - lse;
    outp[n * 2 + 1] = l1 - lse;
}

// ---------------- launch ------------------------------------------------------
extern "C" void kernel_launch(void* const* d_in, const int* in_sizes, int n_in,
                              void* d_out, int out_size) {
    const float* h     = (const float*)d_in[0];
    const float* hadj  = (const float*)d_in[1];
    const float* w     = (const float*)d_in[2];
    const float* a_src = (const float*)d_in[3];
    const float* a_dst = (const float*)d_in[4];
    const float* fc_w  = (const float*)d_in[5];
    const float* fc_b  = (const float*)d_in[6];
    float* outp = (float*)d_out;

    prep_gemm<<<KH * (NNODE / 64), 256>>>(h, w);
    prep_rowstats<<<KH * (NNODE / 256), 256>>>(a_src, a_dst);

    cudaFuncSetAttribute(attn_kernel, cudaFuncAttributeMaxDynamicSharedMemorySize, SMEM_ATTN);
    attn_kernel<<<NK * 64, 512, SMEM_ATTN>>>(hadj);

    final_kernel<<<(NUSER + 127) / 128, 128>>>(fc_w, fc_b, outp);
}

// round 5
// speedup vs baseline: 3.3204x; 1.0721x over previous
#include <cuda_runtime.h>
#include <cuda_bf16.h>
#include <cstdint>

#define DEV_INLINE __device__ __forceinline__

constexpr int NK = 2, NH = 4, NNODE = 4096, ND = 64, NO = 64, NUSER = 4000;
constexpr int KH = NK * NH;
constexpr int JCHUNK = 64, NCHUNK = NNODE / JCHUNK;   // 64 chunks
constexpr int PSTR = 144;                             // padded bf16 tile row stride (bytes)

// ---------------- scratch ----------------------------------------------------
__device__ __nv_bfloat16 g_hpT[(size_t)KH * NO * NNODE];   // V^T bf16: (k,h,o,n)
__device__ float g_srcv[KH * NNODE], g_ea[KH * NNODE], g_ea2[KH * NNODE];
__device__ float g_dstv[KH * NNODE], g_eb[KH * NNODE], g_eb2[KH * NNODE];
__device__ float2 g_plog[NK][NNODE];                       // partial logits per kind

// ---------------- helpers ----------------------------------------------------
DEV_INLINE uint32_t smem_u32(const void* p) {
    uint32_t a;
    asm("{ .reg .u64 t; cvta.to.shared.u64 t, %1; cvt.u32.u64 %0, t; }" : "=r"(a) : "l"(p));
    return a;
}
DEV_INLINE void ldsm4(uint32_t* r, uint32_t a) {
    asm volatile("ldmatrix.sync.aligned.m8n8.x4.shared.b16 {%0,%1,%2,%3}, [%4];"
                 : "=r"(r[0]), "=r"(r[1]), "=r"(r[2]), "=r"(r[3]) : "r"(a));
}
DEV_INLINE void mma16816(float* c, const uint32_t* a, const uint32_t* b) {
    asm volatile(
        "mma.sync.aligned.m16n8k16.row.col.f32.bf16.bf16.f32 "
        "{%0,%1,%2,%3}, {%4,%5,%6,%7}, {%8,%9}, {%0,%1,%2,%3};"
        : "+f"(c[0]), "+f"(c[1]), "+f"(c[2]), "+f"(c[3])
        : "r"(a[0]), "r"(a[1]), "r"(a[2]), "r"(a[3]), "r"(b[0]), "r"(b[1]));
}
DEV_INLINE uint32_t cvt_bf16x2(float hi, float lo) {
    uint32_t r;
    asm("cvt.rn.bf16x2.f32 %0, %1, %2;" : "=r"(r) : "f"(hi), "f"(lo));
    return r;
}
DEV_INLINE float tanh_fast(float x) {
    float y;
    asm("tanh.approx.f32 %0, %1;" : "=f"(y) : "f"(x));
    return y;
}
DEV_INLINE void cpasync16(uint32_t dst, const void* src) {
    asm volatile("cp.async.cg.shared.global [%0], [%1], 16;" :: "r"(dst), "l"(src));
}
DEV_INLINE void cpasync_commit() { asm volatile("cp.async.commit_group;" ::: "memory"); }
DEV_INLINE void cpasync_wait0()  { asm volatile("cp.async.wait_group 0;" ::: "memory"); }

// ------- stage 1: h_prime GEMM + bf16 V^T + fused rowstats (tanh dots) -------
__global__ void prep_gemm(const float* __restrict__ hin, const float* __restrict__ w,
                          const float* __restrict__ a_src, const float* __restrict__ a_dst) {
    __shared__ float s_w[ND][NO];
    __shared__ float s_h[64][66];
    __shared__ float sas[NO], sad[NO];
    int t = threadIdx.x;
    int kh = blockIdx.x >> 6;
    int n0 = (blockIdx.x & 63) * 64;
    const float* wk = w + (size_t)kh * ND * NO;
    const float* hsrc = hin + (size_t)n0 * ND;
    for (int q = t; q < ND * NO; q += 256) ((float*)s_w)[q] = wk[q];
    for (int q = t; q < 64 * ND; q += 256) s_h[q >> 6][q & 63] = hsrc[q];
    if (t < NO)          sas[t] = a_src[kh * NO + t];
    else if (t < 2 * NO) sad[t - NO] = a_dst[kh * NO + t - NO];
    __syncthreads();
    int tr = t >> 4, tc = t & 15;
    float acc[4][4] = {};
    for (int d = 0; d < ND; d++) {
        float4 wv = *(const float4*)&s_w[d][tc * 4];
        #pragma unroll
        for (int r = 0; r < 4; r++) {
            float hv = s_h[tr * 4 + r][d];
            acc[r][0] += hv * wv.x; acc[r][1] += hv * wv.y;
            acc[r][2] += hv * wv.z; acc[r][3] += hv * wv.w;
        }
    }
    __syncthreads();
    #pragma unroll
    for (int r = 0; r < 4; r++)
        #pragma unroll
        for (int c = 0; c < 4; c++)
            s_h[tc * 4 + c][tr * 4 + r] = acc[r][c];   // s_h[o][n_local]
    __syncthreads();
    // bf16 transposed V write
    {
        int o = t >> 2, seg = t & 3;
        uint32_t pk[8];
        #pragma unroll
        for (int e = 0; e < 8; e++)
            pk[e] = cvt_bf16x2(s_h[o][seg * 16 + 2 * e + 1], s_h[o][seg * 16 + 2 * e]);
        uint4* dst = (uint4*)((char*)g_hpT + (((size_t)kh * NO + o) * NNODE + n0 + seg * 16) * 2);
        dst[0] = make_uint4(pk[0], pk[1], pk[2], pk[3]);
        dst[1] = make_uint4(pk[4], pk[5], pk[6], pk[7]);
    }
    // fused rowstats: threads 0..63 each own one node
    if (t < 64) {
        float ss = 0.f, dd = 0.f;
        #pragma unroll
        for (int o = 0; o < NO; o++) {
            float tv = tanh_fast(s_h[o][t]);
            ss += tv * sas[o];
            dd += tv * sad[o];
        }
        int idx = kh * NNODE + n0 + t;
        g_srcv[idx] = ss; g_ea[idx] = expf(ss); g_ea2[idx] = expf(0.2f * ss);
        g_dstv[idx] = dd; g_eb[idx] = expf(dd); g_eb2[idx] = expf(0.2f * dd);
    }
}

// ---------------- stage 2: fused attention (construct + HMMA + fc) -----------
constexpr int OFF_SRCPK = 0;                 // [4][64] float4 (srcv, ea, ea2, _)
constexpr int OFF_DTBL  = 4096;              // [2][3][4][64] f32
constexpr int OFF_FCW   = 10240;             // [2][128] f32
constexpr int OFF_P     = 11264;             // [2][4] x 64*PSTR bf16
constexpr int OFF_V     = 84992;             // [2][4] x 64*PSTR bf16
constexpr int SMEM_ATTN = 158720;
constexpr int OFF_OUT   = OFF_P;             // epilogue reuse: [4][64][64] f32
constexpr int OFF_DEN   = OFF_P + 65536;     // [4][64][2] f32

__global__ void __launch_bounds__(512, 1)
attn_kernel(const float* __restrict__ adj, const float* __restrict__ fcw) {
    extern __shared__ char sm[];
    uint32_t sb = smem_u32(sm);
    int t = threadIdx.x, w = t >> 5, lane = t & 31;
    int k = blockIdx.x >> 6;
    int i0 = (blockIdx.x & 63) * 64;

    int h = w >> 2, ih = (w >> 1) & 1, oh = w & 1;   // mma role
    int gr = lane >> 2, lq = lane & 3;
    uint32_t bones = (gr == 0) ? 0x3F803F80u : 0u;

    const float* adjk = adj + (size_t)k * NNODE * NNODE;

    // ---- stage src tables + fc weights (once) ----
    if (t < 256) {
        int hh = t >> 6, i = t & 63;
        int idx = (k * NH + hh) * NNODE + i0 + i;
        *(float4*)(sm + OFF_SRCPK + t * 16) =
            make_float4(g_srcv[idx], g_ea[idx], g_ea2[idx], 0.f);
    } else if (t < 384) {
        int q = t - 256;                         // 0..127
        *(float*)(sm + OFF_FCW + q * 4)       = fcw[k * 64 + (q & 63) + (q >> 6) * 128];
    }
    auto stage_dst = [&](int c) {
        if (c >= NCHUNK) return;
        int buf = c & 1;
        if (t < 384) {
            #pragma unroll
            for (int u = 0; u < 2; u++) {
                int q = t * 2 + u;
                int arr = q >> 8, rest = q & 255, hh = rest >> 6, j = rest & 63;
                const float* sa = (arr == 0) ? g_dstv : (arr == 1) ? g_eb : g_eb2;
                *(float*)(sm + OFF_DTBL + buf * 3072 + (arr * 4 + hh) * 256 + j * 4) =
                    sa[(k * NH + hh) * NNODE + c * JCHUNK + j];
            }
        }
    };
    stage_dst(0);

    float acc[2][4][4];
    float dacc[2][4];
    #pragma unroll
    for (int a = 0; a < 2; a++) {
        #pragma unroll
        for (int b = 0; b < 4; b++) {
            #pragma unroll
            for (int e = 0; e < 4; e++) acc[a][b][e] = 0.f;
            dacc[a][b] = 0.f;
        }
    }

    uint32_t aoff = (uint32_t)(((lane & 7) + 8 * ((lane >> 3) & 1)) * PSTR + (lane >> 4) * 16);
    uint32_t boff = (uint32_t)(((lane & 7) + 8 * ((lane >> 4) & 1)) * PSTR + ((lane >> 3) & 1) * 16);

    auto mma_chunk = [&](int vbuf) {
        uint32_t pb = sb + OFF_P + (vbuf * 4 + h) * 9216 + ih * 32 * PSTR;
        uint32_t vb = sb + OFF_V + (vbuf * 4 + h) * 9216 + oh * 32 * PSTR;
        #pragma unroll
        for (int ks = 0; ks < 4; ks++) {
            uint32_t a0[4], a1[4], b0[4], b1[4];
            ldsm4(a0, pb + aoff + ks * 32);
            ldsm4(a1, pb + 16 * PSTR + aoff + ks * 32);
            ldsm4(b0, vb + boff + ks * 32);
            ldsm4(b1, vb + 16 * PSTR + boff + ks * 32);
            mma16816(acc[0][0], a0, b0 + 0); mma16816(acc[0][1], a0, b0 + 2);
            mma16816(acc[0][2], a0, b1 + 0); mma16816(acc[0][3], a0, b1 + 2);
            mma16816(acc[1][0], a1, b0 + 0); mma16816(acc[1][1], a1, b0 + 2);
            mma16816(acc[1][2], a1, b1 + 0); mma16816(acc[1][3], a1, b1 + 2);
            if ((ks < 2) == (oh == 0)) {       // den split across oh warps
                uint32_t bo[2] = {bones, bones};
                mma16816(dacc[0], a0, bo);
                mma16816(dacc[1], a1, bo);
            }
        }
    };

    // preload adj for chunk 0
    float2 adjc[4];
    #pragma unroll
    for (int s = 0; s < 4; s++)
        adjc[s] = *(const float2*)(adjk + (size_t)(i0 + 4 * w + s) * NNODE + 2 * lane);
    __syncthreads();

    for (int c = 0; c < NCHUNK; c++) {
        int buf = c & 1;
        int j0 = c * JCHUNK;
        // prefetch adj one chunk ahead
        float2 adjn[4];
        if (c + 1 < NCHUNK) {
            #pragma unroll
            for (int s = 0; s < 4; s++)
                adjn[s] = *(const float2*)(adjk + (size_t)(i0 + 4 * w + s) * NNODE +
                                           (j0 + JCHUNK) + 2 * lane);
        }
        // V staging via cp.async (used by mma in next iteration)
        #pragma unroll
        for (int u = 0; u < 4; u++) {
            int q = t + 512 * u;
            int seg = q & 7, o = (q >> 3) & 63, hh = q >> 9;
            const char* src = (const char*)g_hpT +
                (((size_t)(k * NH + hh) * NO + o) * NNODE + j0) * 2 + seg * 16;
            cpasync16(sb + OFF_V + (buf * 4 + hh) * 9216 + o * PSTR + seg * 16, src);
        }
        cpasync_commit();

        if (c > 0) mma_chunk((c - 1) & 1);
        stage_dst(c + 1);

        float2 dv[4], ep[4], eq[4];
        #pragma unroll
        for (int hh = 0; hh < 4; hh++) {
            dv[hh] = *(float2*)(sm + OFF_DTBL + buf * 3072 + (0 + hh) * 256 + lane * 8);
            ep[hh] = *(float2*)(sm + OFF_DTBL + buf * 3072 + (4 + hh) * 256 + lane * 8);
            eq[hh] = *(float2*)(sm + OFF_DTBL + buf * 3072 + (8 + hh) * 256 + lane * 8);
        }
        #pragma unroll
        for (int s = 0; s < 4; s++) {
            int i = 4 * w + s;
            #pragma unroll
            for (int hh = 0; hh < 4; hh++) {
                float4 sp = *(float4*)(sm + OFF_SRCPK + (hh * 64 + i) * 16);
                float sg0 = sp.x + dv[hh].x, sg1 = sp.x + dv[hh].y;
                float e0 = (sg0 >= 0.f) ? sp.y * ep[hh].x : sp.z * eq[hh].x;
                float e1 = (sg1 >= 0.f) ? sp.y * ep[hh].y : sp.z * eq[hh].y;
                *(uint32_t*)(sm + OFF_P + (buf * 4 + hh) * 9216 + i * PSTR + lane * 4) =
                    cvt_bf16x2(adjc[s].y * e1, adjc[s].x * e0);
            }
        }
        cpasync_wait0();
        __syncthreads();
        #pragma unroll
        for (int s = 0; s < 4; s++) adjc[s] = adjn[s];
    }
    mma_chunk((NCHUNK - 1) & 1);
    __syncthreads();

    // ---- epilogue: fragments -> smem, normalize + head-mean + fc partial ----
    #pragma unroll
    for (int mt = 0; mt < 2; mt++) {
        #pragma unroll
        for (int nt = 0; nt < 4; nt++) {
            int row = ih * 32 + mt * 16 + gr;
            int col = oh * 32 + nt * 8 + 2 * lq;
            *(float2*)(sm + OFF_OUT + ((h * 64 + row) * 64 + col) * 4) =
                make_float2(acc[mt][nt][0], acc[mt][nt][1]);
            *(float2*)(sm + OFF_OUT + ((h * 64 + row + 8) * 64 + col) * 4) =
                make_float2(acc[mt][nt][2], acc[mt][nt][3]);
        }
        {
            int row = ih * 32 + mt * 16 + gr;
            *(float*)(sm + OFF_DEN + ((h * 64 + row) * 2 + oh) * 4) = dacc[mt][0];
            *(float*)(sm + OFF_DEN + ((h * 64 + row + 8) * 2 + oh) * 4) = dacc[mt][2];
        }
    }
    __syncthreads();
    {
        int i = t >> 3, ob = (t & 7) * 8;
        float res[8] = {};
        #pragma unroll
        for (int hh = 0; hh < 4; hh++) {
            float2 dpair = *(float2*)(sm + OFF_DEN + (hh * 64 + i) * 8);
            float inv = 0.25f / (dpair.x + dpair.y);
            float4 x0 = *(float4*)(sm + OFF_OUT + ((hh * 64 + i) * 64 + ob) * 4);
            float4 x1 = *(float4*)(sm + OFF_OUT + ((hh * 64 + i) * 64 + ob + 4) * 4);
            res[0] += x0.x * inv; res[1] += x0.y * inv; res[2] += x0.z * inv; res[3] += x0.w * inv;
            res[4] += x1.x * inv; res[5] += x1.y * inv; res[6] += x1.z * inv; res[7] += x1.w * inv;
        }
        // fc partials for this (i, ob..ob+7)
        float p0 = 0.f, p1 = 0.f;
        #pragma unroll
        for (int e = 0; e < 8; e++) {
            p0 += res[e] * *(float*)(sm + OFF_FCW + (ob + e) * 4);
            p1 += res[e] * *(float*)(sm + OFF_FCW + (64 + ob + e) * 4);
        }
        #pragma unroll
        for (int off = 1; off < 8; off <<= 1) {
            p0 += __shfl_xor_sync(0xFFFFFFFFu, p0, off);
            p1 += __shfl_xor_sync(0xFFFFFFFFu, p1, off);
        }
        if ((t & 7) == 0) g_plog[k][i0 + i] = make_float2(p0, p1);
    }
}

// ---------------- stage 3: combine partial logits + log_softmax --------------
__global__ void final_kernel(const float* __restrict__ fcb, float* __restrict__ outp) {
    int n = blockIdx.x * 256 + threadIdx.x;
    if (n >= NUSER) return;
    float2 a = g_plog[0][n], b = g_plog[1][n];
    float l0 = a.x + b.x + __ldg(&fcb[0]);
    float l1 = a.y + b.y + __ldg(&fcb[1]);
    float m = fmaxf(l0, l1);
    float lse = m + logf(expf(l0 - m) + expf(l1 - m));
    outp[n * 2]     = l0 - lse;
    outp[n * 2 + 1] = l1 - lse;
}

// ---------------- launch ------------------------------------------------------
extern "C" void kernel_launch(void* const* d_in, const int* in_sizes, int n_in,
                              void* d_out, int out_size) {
    const float* h     = (const float*)d_in[0];
    const float* hadj  = (const float*)d_in[1];
    const float* w     = (const float*)d_in[2];
    const float* a_src = (const float*)d_in[3];
    const float* a_dst = (const float*)d_in[4];
    const float* fc_w  = (const float*)d_in[5];
    const float* fc_b  = (const float*)d_in[6];
    float* outp = (float*)d_out;

    prep_gemm<<<KH * (NNODE / 64), 256>>>(h, w, a_src, a_dst);

    cudaFuncSetAttribute(attn_kernel, cudaFuncAttributeMaxDynamicSharedMemorySize, SMEM_ATTN);
    attn_kernel<<<NK * 64, 512, SMEM_ATTN>>>(hadj, fc_w);

    final_kernel<<<(NUSER + 255) / 256, 256>>>(fc_b, outp);
}